// round 1
// baseline (speedup 1.0000x reference)
#include <cuda_runtime.h>
#include <math_constants.h>

#define NMAX 100000
#define EMAXN 1600000
#define KF 256
#define HD 128
#define NHEAD 4

// ---------------- scratch (device globals; no allocs allowed) ----------------
__device__ float g_ft[(size_t)NMAX * HD];     // projected features [N,128]  (51.2 MB)
__device__ float g_el[NMAX * NHEAD];          // left logits  [N,4]
__device__ float g_er[NMAX * NHEAD];          // right logits [N,4]
__device__ float g_emax[NMAX * NHEAD];        // segment max  [N,4]
__device__ float g_asum[NMAX * NHEAD];        // segment sum  [N,4]
__device__ float g_a[(size_t)EMAXN * NHEAD];  // unnormalized attention [E,4] (25.6 MB)

// ---------------- helpers ----------------
__device__ __forceinline__ void atomicMaxFloat(float* addr, float value) {
    // IEEE trick: signed-int max for non-negative, unsigned-int min for negative.
    if (value >= 0.f) atomicMax((int*)addr, __float_as_int(value));
    else              atomicMin((unsigned int*)addr, __float_as_uint(value));
}

// ---------------- init: emax=-inf, asum=0 ----------------
__global__ void init_kernel(int nh) {
    int i = blockIdx.x * blockDim.x + threadIdx.x;
    if (i < nh) {
        g_emax[i] = -CUDART_INF_F;
        g_asum[i] = 0.f;
    }
}

// ---------------- SGEMM: g_ft = feat[M,256] @ fc_w[128,256]^T ----------------
// 128x128 block tile, BK=8, 256 threads, 8x8 per-thread register tile.
__global__ __launch_bounds__(256) void sgemm_kernel(const float* __restrict__ A,
                                                    const float* __restrict__ B,
                                                    int M) {
    __shared__ float As[8][128];
    __shared__ float Bs[8][128];

    const int tid  = threadIdx.x;
    const int row0 = blockIdx.x * 128;
    const int lrow = tid >> 1;         // 0..127
    const int lk   = (tid & 1) * 4;    // 0 or 4
    const int tx   = tid & 15;         // col group 0..15
    const int ty   = tid >> 4;         // row group 0..15

    float acc[8][8];
#pragma unroll
    for (int i = 0; i < 8; i++)
#pragma unroll
        for (int j = 0; j < 8; j++) acc[i][j] = 0.f;

    const int  arow   = row0 + lrow;
    const bool avalid = (arow < M);

    for (int kt = 0; kt < KF; kt += 8) {
        float4 av = avalid ? *(const float4*)&A[(size_t)arow * KF + kt + lk]
                           : make_float4(0.f, 0.f, 0.f, 0.f);
        float4 bv = *(const float4*)&B[(size_t)lrow * KF + kt + lk];

        As[lk + 0][lrow] = av.x; As[lk + 1][lrow] = av.y;
        As[lk + 2][lrow] = av.z; As[lk + 3][lrow] = av.w;
        Bs[lk + 0][lrow] = bv.x; Bs[lk + 1][lrow] = bv.y;
        Bs[lk + 2][lrow] = bv.z; Bs[lk + 3][lrow] = bv.w;
        __syncthreads();

#pragma unroll
        for (int k = 0; k < 8; k++) {
            float4 a0 = *(const float4*)&As[k][ty * 8];
            float4 a1 = *(const float4*)&As[k][ty * 8 + 4];
            float4 b0 = *(const float4*)&Bs[k][tx * 8];
            float4 b1 = *(const float4*)&Bs[k][tx * 8 + 4];
            float ar[8] = {a0.x, a0.y, a0.z, a0.w, a1.x, a1.y, a1.z, a1.w};
            float br[8] = {b0.x, b0.y, b0.z, b0.w, b1.x, b1.y, b1.z, b1.w};
#pragma unroll
            for (int i = 0; i < 8; i++)
#pragma unroll
                for (int j = 0; j < 8; j++) acc[i][j] = fmaf(ar[i], br[j], acc[i][j]);
        }
        __syncthreads();
    }

#pragma unroll
    for (int i = 0; i < 8; i++) {
        int r = row0 + ty * 8 + i;
        if (r < M) {
            float4 o0 = make_float4(acc[i][0], acc[i][1], acc[i][2], acc[i][3]);
            float4 o1 = make_float4(acc[i][4], acc[i][5], acc[i][6], acc[i][7]);
            *(float4*)&g_ft[(size_t)r * HD + tx * 8]     = o0;
            *(float4*)&g_ft[(size_t)r * HD + tx * 8 + 4] = o1;
        }
    }
}

// ---------------- per-node attention logits el/er ----------------
__global__ void elr_kernel(const float* __restrict__ attn_l,
                           const float* __restrict__ attn_r, int nh) {
    int idx = blockIdx.x * blockDim.x + threadIdx.x;
    if (idx >= nh) return;
    int n = idx >> 2, h = idx & 3;
    const float4* f  = (const float4*)&g_ft[(size_t)n * HD + h * 32];
    const float4* wl = (const float4*)&attn_l[h * 32];
    const float4* wr = (const float4*)&attn_r[h * 32];
    float el = 0.f, er = 0.f;
#pragma unroll
    for (int i = 0; i < 8; i++) {
        float4 fv = f[i], lv = wl[i], rv = wr[i];
        el += fv.x * lv.x + fv.y * lv.y + fv.z * lv.z + fv.w * lv.w;
        er += fv.x * rv.x + fv.y * rv.y + fv.z * rv.z + fv.w * rv.w;
    }
    g_el[idx] = el;
    g_er[idx] = er;
}

// ---------------- edge pass 1: segment max of leaky_relu(el[src]+er[dst]) ----
__global__ void edge_max_kernel(const int* __restrict__ src,
                                const int* __restrict__ dst, int E) {
    int e = blockIdx.x * blockDim.x + threadIdx.x;
    if (e >= E) return;
    int s = src[e], d = dst[e];
    float4 el4 = *(const float4*)&g_el[s * 4];
    float4 er4 = *(const float4*)&g_er[d * 4];
    float* em = &g_emax[d * 4];
    float v;
    v = el4.x + er4.x; v = v > 0.f ? v : 0.2f * v; atomicMaxFloat(em + 0, v);
    v = el4.y + er4.y; v = v > 0.f ? v : 0.2f * v; atomicMaxFloat(em + 1, v);
    v = el4.z + er4.z; v = v > 0.f ? v : 0.2f * v; atomicMaxFloat(em + 2, v);
    v = el4.w + er4.w; v = v > 0.f ? v : 0.2f * v; atomicMaxFloat(em + 3, v);
}

// ---------------- edge pass 2: a = exp(e - emax[dst]); asum += a ------------
__global__ void edge_exp_kernel(const int* __restrict__ src,
                                const int* __restrict__ dst, int E) {
    int e = blockIdx.x * blockDim.x + threadIdx.x;
    if (e >= E) return;
    int s = src[e], d = dst[e];
    float4 el4 = *(const float4*)&g_el[s * 4];
    float4 er4 = *(const float4*)&g_er[d * 4];
    float4 em4 = *(const float4*)&g_emax[d * 4];
    float v;
    float4 a4;
    v = el4.x + er4.x; v = v > 0.f ? v : 0.2f * v; a4.x = expf(v - em4.x);
    v = el4.y + er4.y; v = v > 0.f ? v : 0.2f * v; a4.y = expf(v - em4.y);
    v = el4.z + er4.z; v = v > 0.f ? v : 0.2f * v; a4.z = expf(v - em4.z);
    v = el4.w + er4.w; v = v > 0.f ? v : 0.2f * v; a4.w = expf(v - em4.w);
    *(float4*)&g_a[(size_t)e * 4] = a4;
    atomicAdd((float4*)&g_asum[d * 4], a4);   // sm_90+ vector atomic
}

// ---------------- edge pass 3: out[dst] += (a/asum[dst]) * ft[src] ----------
// One warp per edge; lane handles 4 contiguous floats of the 128-wide row.
__global__ __launch_bounds__(256) void aggregate_kernel(const int* __restrict__ src,
                                                        const int* __restrict__ dst,
                                                        float* __restrict__ out, int E) {
    int w    = (blockIdx.x * blockDim.x + threadIdx.x) >> 5;
    int lane = threadIdx.x & 31;
    if (w >= E) return;
    int s = src[w], d = dst[w];
    int h = lane >> 3;                       // head owning this lane's 4 floats
    float av = g_a[(size_t)w * 4 + h];       // broadcast within 8-lane groups
    float sv = g_asum[d * 4 + h];
    float c  = av / sv;
    float4 v = *(const float4*)&g_ft[(size_t)s * HD + lane * 4];
    v.x *= c; v.y *= c; v.z *= c; v.w *= c;
    atomicAdd((float4*)&out[(size_t)d * HD + lane * 4], v);  // vector RED
}

// ---------------- launch ----------------
extern "C" void kernel_launch(void* const* d_in, const int* in_sizes, int n_in,
                              void* d_out, int out_size) {
    const float* feat   = (const float*)d_in[0];
    const float* fc_w   = (const float*)d_in[1];
    const float* attn_l = (const float*)d_in[2];
    const float* attn_r = (const float*)d_in[3];
    const int*   src    = (const int*)d_in[4];
    const int*   dst    = (const int*)d_in[5];
    float*       out    = (float*)d_out;

    int M = in_sizes[0] / KF;   // number of nodes
    int E = in_sizes[4];        // number of edges
    int NH = M * NHEAD;

    cudaMemsetAsync(d_out, 0, (size_t)out_size * sizeof(float), 0);
    init_kernel<<<(NH + 255) / 256, 256>>>(NH);
    sgemm_kernel<<<(M + 127) / 128, 256>>>(feat, fc_w, M);
    elr_kernel<<<(NH + 255) / 256, 256>>>(attn_l, attn_r, NH);
    edge_max_kernel<<<(E + 255) / 256, 256>>>(src, dst, E);
    edge_exp_kernel<<<(E + 255) / 256, 256>>>(src, dst, E);
    {
        long long threads = (long long)E * 32;
        int blocks = (int)((threads + 255) / 256);
        aggregate_kernel<<<blocks, 256>>>(src, dst, out, E);
    }
}

// round 2
// speedup vs baseline: 1.9035x; 1.9035x over previous
#include <cuda_runtime.h>

#define NMAX 100000
#define EMAXN 1600000
#define KF 256
#define HD 128

// ---------------- scratch (device globals; no allocs allowed) ----------------
__device__ float g_ft[(size_t)NMAX * HD];   // projected features [N,128] (51.2 MB)
__device__ float g_el[NMAX * 4];            // left logits  [N,4]
__device__ float g_er[NMAX * 4];            // right logits [N,4]
__device__ int   g_cnt[NMAX];               // histogram, then scatter cursor
__device__ int   g_off[NMAX + 1];           // CSR offsets by dst
__device__ int   g_bsum[512];               // block sums for scan
__device__ int   g_esrc[EMAXN];             // src ids bucketed by dst

// ================= SGEMM + fused el/er epilogue ==============================
// g_ft = feat[M,256] @ fc_w[128,256]^T ; el/er = ft . attn (flat 128 vectors)
__global__ __launch_bounds__(256) void sgemm_kernel(const float* __restrict__ A,
                                                    const float* __restrict__ B,
                                                    const float* __restrict__ attn_l,
                                                    const float* __restrict__ attn_r,
                                                    int M) {
    __shared__ float As[8][128];
    __shared__ float Bs[8][128];

    const int tid  = threadIdx.x;
    const int row0 = blockIdx.x * 128;
    const int lrow = tid >> 1;         // 0..127
    const int lk   = (tid & 1) * 4;    // 0 or 4
    const int tx   = tid & 15;         // col group 0..15
    const int ty   = tid >> 4;         // row group 0..15

    float acc[8][8];
#pragma unroll
    for (int i = 0; i < 8; i++)
#pragma unroll
        for (int j = 0; j < 8; j++) acc[i][j] = 0.f;

    const int  arow   = row0 + lrow;
    const bool avalid = (arow < M);

    for (int kt = 0; kt < KF; kt += 8) {
        float4 av = avalid ? *(const float4*)&A[(size_t)arow * KF + kt + lk]
                           : make_float4(0.f, 0.f, 0.f, 0.f);
        float4 bv = *(const float4*)&B[(size_t)lrow * KF + kt + lk];

        As[lk + 0][lrow] = av.x; As[lk + 1][lrow] = av.y;
        As[lk + 2][lrow] = av.z; As[lk + 3][lrow] = av.w;
        Bs[lk + 0][lrow] = bv.x; Bs[lk + 1][lrow] = bv.y;
        Bs[lk + 2][lrow] = bv.z; Bs[lk + 3][lrow] = bv.w;
        __syncthreads();

#pragma unroll
        for (int k = 0; k < 8; k++) {
            float4 a0 = *(const float4*)&As[k][ty * 8];
            float4 a1 = *(const float4*)&As[k][ty * 8 + 4];
            float4 b0 = *(const float4*)&Bs[k][tx * 8];
            float4 b1 = *(const float4*)&Bs[k][tx * 8 + 4];
            float ar[8] = {a0.x, a0.y, a0.z, a0.w, a1.x, a1.y, a1.z, a1.w};
            float br[8] = {b0.x, b0.y, b0.z, b0.w, b1.x, b1.y, b1.z, b1.w};
#pragma unroll
            for (int i = 0; i < 8; i++)
#pragma unroll
                for (int j = 0; j < 8; j++) acc[i][j] = fmaf(ar[i], br[j], acc[i][j]);
        }
        __syncthreads();
    }

    // attn weights for this thread's 8 columns (all within one head: tx*8..tx*8+7)
    float wl[8], wr[8];
#pragma unroll
    for (int j = 0; j < 8; j++) { wl[j] = attn_l[tx * 8 + j]; wr[j] = attn_r[tx * 8 + j]; }
    const int h = tx >> 2;   // head owning columns [h*32, h*32+32)

#pragma unroll
    for (int i = 0; i < 8; i++) {
        int r = row0 + ty * 8 + i;
        float el = 0.f, er = 0.f;
#pragma unroll
        for (int j = 0; j < 8; j++) { el = fmaf(acc[i][j], wl[j], el); er = fmaf(acc[i][j], wr[j], er); }
        // reduce across the 4 threads (tx%4) covering this head's 32 cols
        el += __shfl_xor_sync(0xffffffffu, el, 1);
        el += __shfl_xor_sync(0xffffffffu, el, 2);
        er += __shfl_xor_sync(0xffffffffu, er, 1);
        er += __shfl_xor_sync(0xffffffffu, er, 2);
        if (r < M) {
            float4 o0 = make_float4(acc[i][0], acc[i][1], acc[i][2], acc[i][3]);
            float4 o1 = make_float4(acc[i][4], acc[i][5], acc[i][6], acc[i][7]);
            *(float4*)&g_ft[(size_t)r * HD + tx * 8]     = o0;
            *(float4*)&g_ft[(size_t)r * HD + tx * 8 + 4] = o1;
            if ((tx & 3) == 0) { g_el[r * 4 + h] = el; g_er[r * 4 + h] = er; }
        }
    }
}

// ================= CSR build: histogram -> scan -> scatter ===================
__global__ void hist_kernel(const int* __restrict__ dst, int E) {
    int e = blockIdx.x * blockDim.x + threadIdx.x;
    if (e < E) atomicAdd(&g_cnt[dst[e]], 1);
}

__global__ void scan1_kernel(int n) {
    __shared__ int sh[256];
    int i = blockIdx.x * 256 + threadIdx.x;
    int v = (i < n) ? g_cnt[i] : 0;
    sh[threadIdx.x] = v;
    __syncthreads();
#pragma unroll
    for (int ofs = 1; ofs < 256; ofs <<= 1) {
        int t = (threadIdx.x >= ofs) ? sh[threadIdx.x - ofs] : 0;
        __syncthreads();
        sh[threadIdx.x] += t;
        __syncthreads();
    }
    if (i < n) g_off[i + 1] = sh[threadIdx.x];
    if (threadIdx.x == 255) g_bsum[blockIdx.x] = sh[255];
}

__global__ void scan2_kernel(int nb) {
    __shared__ int sh[512];
    int t = threadIdx.x;
    int v = (t < nb) ? g_bsum[t] : 0;
    sh[t] = v;
    __syncthreads();
#pragma unroll
    for (int ofs = 1; ofs < 512; ofs <<= 1) {
        int u = (t >= ofs) ? sh[t - ofs] : 0;
        __syncthreads();
        sh[t] += u;
        __syncthreads();
    }
    if (t < nb) g_bsum[t] = sh[t] - v;   // exclusive
}

__global__ void scan3_kernel(int n) {
    int i = blockIdx.x * 256 + threadIdx.x;
    if (i < n) g_off[i + 1] += g_bsum[blockIdx.x];
    if (i == 0) g_off[0] = 0;
}

__global__ void scatter_kernel(const int* __restrict__ src,
                               const int* __restrict__ dst, int E) {
    int e = blockIdx.x * blockDim.x + threadIdx.x;
    if (e >= E) return;
    int d   = dst[e];
    int pos = g_off[d] + atomicAdd(&g_cnt[d], 1);
    g_esrc[pos] = src[e];
}

// ================= fused softmax + aggregate (warp per dst node) =============
// out[d] = sum_e exp(lrelu(el[s]+er[d])) * ft[s]  /  sum_e exp(...)
// (max-subtraction is shift-invariant and logits are O(5); skipped.)
__global__ __launch_bounds__(256) void aggregate_kernel(float* __restrict__ out, int N) {
    int d    = (blockIdx.x * blockDim.x + threadIdx.x) >> 5;
    int lane = threadIdx.x & 31;
    if (d >= N) return;

    int beg = g_off[d], end = g_off[d + 1];
    const int h   = lane >> 3;               // head owning this lane's 4 floats
    const float erd = g_er[d * 4 + h];

    float4 acc = make_float4(0.f, 0.f, 0.f, 0.f);
    float  asum = 0.f;

    for (int p = beg; p < end; ++p) {
        int   s = g_esrc[p];
        float v = g_el[s * 4 + h] + erd;
        v = v > 0.f ? v : 0.2f * v;
        float a = __expf(v);
        asum += a;
        float4 f = *(const float4*)&g_ft[(size_t)s * HD + lane * 4];
        acc.x = fmaf(a, f.x, acc.x);
        acc.y = fmaf(a, f.y, acc.y);
        acc.z = fmaf(a, f.z, acc.z);
        acc.w = fmaf(a, f.w, acc.w);
    }

    float inv = (asum > 0.f) ? (1.f / asum) : 0.f;  // degree-0 nodes -> zeros
    acc.x *= inv; acc.y *= inv; acc.z *= inv; acc.w *= inv;
    *(float4*)&out[(size_t)d * HD + lane * 4] = acc;
}

// ================= launch ====================================================
extern "C" void kernel_launch(void* const* d_in, const int* in_sizes, int n_in,
                              void* d_out, int out_size) {
    const float* feat   = (const float*)d_in[0];
    const float* fc_w   = (const float*)d_in[1];
    const float* attn_l = (const float*)d_in[2];
    const float* attn_r = (const float*)d_in[3];
    const int*   src    = (const int*)d_in[4];
    const int*   dst    = (const int*)d_in[5];
    float*       out    = (float*)d_out;

    int M = in_sizes[0] / KF;   // nodes
    int E = in_sizes[4];        // edges
    int nblk = (M + 255) / 256;

    void* cnt_ptr = nullptr;
    cudaGetSymbolAddress(&cnt_ptr, g_cnt);

    // CSR build by dst
    cudaMemsetAsync(cnt_ptr, 0, (size_t)M * sizeof(int), 0);
    hist_kernel<<<(E + 255) / 256, 256>>>(dst, E);
    scan1_kernel<<<nblk, 256>>>(M);
    scan2_kernel<<<1, 512>>>(nblk);
    scan3_kernel<<<nblk, 256>>>(M);
    cudaMemsetAsync(cnt_ptr, 0, (size_t)M * sizeof(int), 0);
    scatter_kernel<<<(E + 255) / 256, 256>>>(src, dst, E);

    // projection + fused logits
    sgemm_kernel<<<(M + 127) / 128, 256>>>(feat, fc_w, attn_l, attn_r, M);

    // fused softmax + aggregation, one warp per dst node
    aggregate_kernel<<<(M * 32 + 255) / 256, 256>>>(out, M);
}

// round 3
// speedup vs baseline: 2.7816x; 1.4613x over previous
#include <cuda_runtime.h>

#define NMAX 100000
#define EMAXN 1600000
#define KF 256
#define HD 128

// ---------------- scratch (device globals; no allocs allowed) ----------------
__device__ float g_ft[(size_t)NMAX * HD];   // projected features [N,128] (51.2 MB)
__device__ float g_el[NMAX * 4];            // left logits  [N,4]
__device__ float g_er[NMAX * 4];            // right logits [N,4]
__device__ int   g_cnt[NMAX];               // histogram, then scatter cursor
__device__ int   g_off[NMAX + 1];           // CSR offsets by dst
__device__ int   g_bsum[512];               // block sums for scan
__device__ int   g_esrc[EMAXN];             // src ids bucketed by dst

// ================= tf32 tensor-core GEMM =====================================
// g_ft = feat[M,256] @ fc_w[128,256]^T
// Block tile 128x128, BK=32, 8 warps (2 m x 4 n), warp tile 64x32.
// mma.sync.m16n8k8.row.col.f32.tf32.tf32.f32
#define SMSTRIDE 36   // floats per smem row; bank=(4*row+col)&31 -> conflict-free frags

__device__ __forceinline__ unsigned f2tf32(float f) {
    unsigned r;
    asm("cvt.rna.tf32.f32 %0, %1;" : "=r"(r) : "f"(f));
    return r;
}

__global__ __launch_bounds__(256) void mma_gemm_kernel(const float* __restrict__ A,
                                                       const float* __restrict__ B,
                                                       int M) {
    __shared__ unsigned As[128 * SMSTRIDE];
    __shared__ unsigned Bs[128 * SMSTRIDE];

    const int tid    = threadIdx.x;
    const int wid    = tid >> 5;
    const int lane   = tid & 31;
    const int warp_m = wid >> 2;      // 0..1
    const int warp_n = wid & 3;       // 0..3
    const int g      = lane >> 2;     // group 0..7
    const int tg     = lane & 3;      // 0..3

    const int row0 = blockIdx.x * 128;

    // staging assignment: thread covers rows (t>>2) and (t>>2)+64, f4 slots (t&3), (t&3)+4
    const int lr  = tid >> 2;         // 0..63
    const int lc4 = (tid & 3) * 4;    // float4 col offset: 0,4,8,12

    float c[4][4][4];
#pragma unroll
    for (int i = 0; i < 4; i++)
#pragma unroll
        for (int j = 0; j < 4; j++)
#pragma unroll
            for (int k = 0; k < 4; k++) c[i][j][k] = 0.f;

    for (int kt = 0; kt < KF; kt += 32) {
        // ---- stage A (2 rows x 2 float4 per thread), guarded ----
#pragma unroll
        for (int rr = 0; rr < 2; rr++) {
            int gr = row0 + lr + rr * 64;
            bool ok = (gr < M);
#pragma unroll
            for (int cc = 0; cc < 2; cc++) {
                int col = lc4 + cc * 16;
                float4 v = ok ? *(const float4*)&A[(size_t)gr * KF + kt + col]
                              : make_float4(0.f, 0.f, 0.f, 0.f);
                unsigned* p = &As[(lr + rr * 64) * SMSTRIDE + col];
                p[0] = f2tf32(v.x); p[1] = f2tf32(v.y);
                p[2] = f2tf32(v.z); p[3] = f2tf32(v.w);
            }
        }
        // ---- stage B (fc_w is 128 x 256, always in range) ----
#pragma unroll
        for (int rr = 0; rr < 2; rr++) {
            int gr = lr + rr * 64;
#pragma unroll
            for (int cc = 0; cc < 2; cc++) {
                int col = lc4 + cc * 16;
                float4 v = *(const float4*)&B[(size_t)gr * KF + kt + col];
                unsigned* p = &Bs[gr * SMSTRIDE + col];
                p[0] = f2tf32(v.x); p[1] = f2tf32(v.y);
                p[2] = f2tf32(v.z); p[3] = f2tf32(v.w);
            }
        }
        __syncthreads();

#pragma unroll
        for (int k8 = 0; k8 < 32; k8 += 8) {
            unsigned a[4][4], b[4][2];
#pragma unroll
            for (int mt = 0; mt < 4; mt++) {
                int mb = warp_m * 64 + mt * 16;
                a[mt][0] = As[(mb + g)     * SMSTRIDE + k8 + tg];
                a[mt][1] = As[(mb + g + 8) * SMSTRIDE + k8 + tg];
                a[mt][2] = As[(mb + g)     * SMSTRIDE + k8 + tg + 4];
                a[mt][3] = As[(mb + g + 8) * SMSTRIDE + k8 + tg + 4];
            }
#pragma unroll
            for (int nt = 0; nt < 4; nt++) {
                int nb = warp_n * 32 + nt * 8;
                b[nt][0] = Bs[(nb + g) * SMSTRIDE + k8 + tg];
                b[nt][1] = Bs[(nb + g) * SMSTRIDE + k8 + tg + 4];
            }
#pragma unroll
            for (int mt = 0; mt < 4; mt++)
#pragma unroll
                for (int nt = 0; nt < 4; nt++) {
                    asm volatile(
                        "mma.sync.aligned.m16n8k8.row.col.f32.tf32.tf32.f32 "
                        "{%0,%1,%2,%3}, {%4,%5,%6,%7}, {%8,%9}, {%0,%1,%2,%3};\n"
                        : "+f"(c[mt][nt][0]), "+f"(c[mt][nt][1]),
                          "+f"(c[mt][nt][2]), "+f"(c[mt][nt][3])
                        : "r"(a[mt][0]), "r"(a[mt][1]), "r"(a[mt][2]), "r"(a[mt][3]),
                          "r"(b[nt][0]), "r"(b[nt][1]));
                }
        }
        __syncthreads();
    }

    // ---- epilogue: c0,c1 -> (row, col..col+1); c2,c3 -> (row+8, ...) ----
#pragma unroll
    for (int mt = 0; mt < 4; mt++) {
        int r0 = row0 + warp_m * 64 + mt * 16 + g;
#pragma unroll
        for (int nt = 0; nt < 4; nt++) {
            int col = warp_n * 32 + nt * 8 + 2 * tg;
            if (r0 < M)
                *(float2*)&g_ft[(size_t)r0 * HD + col] = make_float2(c[mt][nt][0], c[mt][nt][1]);
            if (r0 + 8 < M)
                *(float2*)&g_ft[(size_t)(r0 + 8) * HD + col] = make_float2(c[mt][nt][2], c[mt][nt][3]);
        }
    }
}

// ================= per-node attention logits el/er ===========================
__global__ void elr_kernel(const float* __restrict__ attn_l,
                           const float* __restrict__ attn_r, int nh) {
    int idx = blockIdx.x * blockDim.x + threadIdx.x;
    if (idx >= nh) return;
    int n = idx >> 2, h = idx & 3;
    const float4* f  = (const float4*)&g_ft[(size_t)n * HD + h * 32];
    const float4* wl = (const float4*)&attn_l[h * 32];
    const float4* wr = (const float4*)&attn_r[h * 32];
    float el = 0.f, er = 0.f;
#pragma unroll
    for (int i = 0; i < 8; i++) {
        float4 fv = f[i], lv = wl[i], rv = wr[i];
        el += fv.x * lv.x + fv.y * lv.y + fv.z * lv.z + fv.w * lv.w;
        er += fv.x * rv.x + fv.y * rv.y + fv.z * rv.z + fv.w * rv.w;
    }
    g_el[idx] = el;
    g_er[idx] = er;
}

// ================= CSR build: histogram -> scan -> scatter ===================
__global__ void hist_kernel(const int* __restrict__ dst, int E) {
    int e = blockIdx.x * blockDim.x + threadIdx.x;
    if (e < E) atomicAdd(&g_cnt[dst[e]], 1);
}

__global__ void scan1_kernel(int n) {
    __shared__ int sh[256];
    int i = blockIdx.x * 256 + threadIdx.x;
    int v = (i < n) ? g_cnt[i] : 0;
    sh[threadIdx.x] = v;
    __syncthreads();
#pragma unroll
    for (int ofs = 1; ofs < 256; ofs <<= 1) {
        int t = (threadIdx.x >= ofs) ? sh[threadIdx.x - ofs] : 0;
        __syncthreads();
        sh[threadIdx.x] += t;
        __syncthreads();
    }
    if (i < n) g_off[i + 1] = sh[threadIdx.x];
    if (threadIdx.x == 255) g_bsum[blockIdx.x] = sh[255];
}

__global__ void scan2_kernel(int nb) {
    __shared__ int sh[512];
    int t = threadIdx.x;
    int v = (t < nb) ? g_bsum[t] : 0;
    sh[t] = v;
    __syncthreads();
#pragma unroll
    for (int ofs = 1; ofs < 512; ofs <<= 1) {
        int u = (t >= ofs) ? sh[t - ofs] : 0;
        __syncthreads();
        sh[t] += u;
        __syncthreads();
    }
    if (t < nb) g_bsum[t] = sh[t] - v;   // exclusive
}

__global__ void scan3_kernel(int n) {
    int i = blockIdx.x * 256 + threadIdx.x;
    if (i < n) g_off[i + 1] += g_bsum[blockIdx.x];
    if (i == 0) g_off[0] = 0;
}

__global__ void scatter_kernel(const int* __restrict__ src,
                               const int* __restrict__ dst, int E) {
    int e = blockIdx.x * blockDim.x + threadIdx.x;
    if (e >= E) return;
    int d   = dst[e];
    int pos = g_off[d] + atomicAdd(&g_cnt[d], 1);
    g_esrc[pos] = src[e];
}

// ================= fused softmax + aggregate (warp per dst node) =============
__global__ __launch_bounds__(256) void aggregate_kernel(float* __restrict__ out, int N) {
    int d    = (blockIdx.x * blockDim.x + threadIdx.x) >> 5;
    int lane = threadIdx.x & 31;
    if (d >= N) return;

    int beg = g_off[d], end = g_off[d + 1];
    const int h     = lane >> 3;
    const float erd = g_er[d * 4 + h];

    float4 acc = make_float4(0.f, 0.f, 0.f, 0.f);
    float  asum = 0.f;

    for (int p = beg; p < end; ++p) {
        int   s = g_esrc[p];
        float v = g_el[s * 4 + h] + erd;
        v = v > 0.f ? v : 0.2f * v;
        float a = __expf(v);
        asum += a;
        float4 f = *(const float4*)&g_ft[(size_t)s * HD + lane * 4];
        acc.x = fmaf(a, f.x, acc.x);
        acc.y = fmaf(a, f.y, acc.y);
        acc.z = fmaf(a, f.z, acc.z);
        acc.w = fmaf(a, f.w, acc.w);
    }

    float inv = (asum > 0.f) ? (1.f / asum) : 0.f;
    acc.x *= inv; acc.y *= inv; acc.z *= inv; acc.w *= inv;
    *(float4*)&out[(size_t)d * HD + lane * 4] = acc;
}

// ================= launch ====================================================
extern "C" void kernel_launch(void* const* d_in, const int* in_sizes, int n_in,
                              void* d_out, int out_size) {
    const float* feat   = (const float*)d_in[0];
    const float* fc_w   = (const float*)d_in[1];
    const float* attn_l = (const float*)d_in[2];
    const float* attn_r = (const float*)d_in[3];
    const int*   src    = (const int*)d_in[4];
    const int*   dst    = (const int*)d_in[5];
    float*       out    = (float*)d_out;

    int M = in_sizes[0] / KF;   // nodes
    int E = in_sizes[4];        // edges
    int nblk = (M + 255) / 256;

    void* cnt_ptr = nullptr;
    cudaGetSymbolAddress(&cnt_ptr, g_cnt);

    // CSR build by dst
    cudaMemsetAsync(cnt_ptr, 0, (size_t)M * sizeof(int), 0);
    hist_kernel<<<(E + 255) / 256, 256>>>(dst, E);
    scan1_kernel<<<nblk, 256>>>(M);
    scan2_kernel<<<1, 512>>>(nblk);
    scan3_kernel<<<nblk, 256>>>(M);
    cudaMemsetAsync(cnt_ptr, 0, (size_t)M * sizeof(int), 0);
    scatter_kernel<<<(E + 255) / 256, 256>>>(src, dst, E);

    // projection (tf32 tensor cores) + logits
    mma_gemm_kernel<<<(M + 127) / 128, 256>>>(feat, fc_w, M);
    elr_kernel<<<(M * 4 + 255) / 256, 256>>>(attn_l, attn_r, M * 4);

    // fused softmax + aggregation, one warp per dst node
    aggregate_kernel<<<(M * 32 + 255) / 256, 256>>>(out, M);
}

// round 4
// speedup vs baseline: 3.0276x; 1.0884x over previous
#include <cuda_runtime.h>
#include <cuda_fp16.h>

#define NMAX 100000
#define EMAXN 1600000
#define KF 256
#define HD 128

// ---------------- scratch (device globals; no allocs allowed) ----------------
__device__ __half g_fth[(size_t)NMAX * HD]; // projected features fp16 [N,128] (25.6 MB)
__device__ float g_el[NMAX * 4];            // left logits  [N,4]
__device__ float g_er[NMAX * 4];            // right logits [N,4]
__device__ int   g_cnt[NMAX];               // histogram, then scatter cursor
__device__ int   g_off[NMAX + 1];           // CSR offsets by dst
__device__ int   g_bsum[512];               // block sums for scan
__device__ int   g_esrc[EMAXN];             // src ids bucketed by dst

// ================= tf32 tensor-core GEMM + fused el/er + fp16 ft =============
// ft = feat[M,256] @ fc_w[128,256]^T ; el/er = ft . attn (flat 128 vectors)
// Block tile 128x128, BK=32, 8 warps (2 m x 4 n), warp tile 64x32.
#define SMSTRIDE 36

__device__ __forceinline__ unsigned f2tf32(float f) {
    unsigned r;
    asm("cvt.rna.tf32.f32 %0, %1;" : "=r"(r) : "f"(f));
    return r;
}

__global__ __launch_bounds__(256) void mma_gemm_kernel(const float* __restrict__ A,
                                                       const float* __restrict__ B,
                                                       const float* __restrict__ attn_l,
                                                       const float* __restrict__ attn_r,
                                                       int M) {
    __shared__ unsigned As[128 * SMSTRIDE];
    __shared__ unsigned Bs[128 * SMSTRIDE];

    const int tid    = threadIdx.x;
    const int wid    = tid >> 5;
    const int lane   = tid & 31;
    const int warp_m = wid >> 2;      // 0..1
    const int warp_n = wid & 3;       // 0..3  (== head owned by this warp)
    const int g      = lane >> 2;     // 0..7
    const int tg     = lane & 3;      // 0..3

    const int row0 = blockIdx.x * 128;
    const int lr   = tid >> 2;        // 0..63
    const int lc4  = (tid & 3) * 4;

    float c[4][4][4];
#pragma unroll
    for (int i = 0; i < 4; i++)
#pragma unroll
        for (int j = 0; j < 4; j++)
#pragma unroll
            for (int k = 0; k < 4; k++) c[i][j][k] = 0.f;

    for (int kt = 0; kt < KF; kt += 32) {
#pragma unroll
        for (int rr = 0; rr < 2; rr++) {
            int gr = row0 + lr + rr * 64;
            bool ok = (gr < M);
#pragma unroll
            for (int cc = 0; cc < 2; cc++) {
                int col = lc4 + cc * 16;
                float4 v = ok ? *(const float4*)&A[(size_t)gr * KF + kt + col]
                              : make_float4(0.f, 0.f, 0.f, 0.f);
                unsigned* p = &As[(lr + rr * 64) * SMSTRIDE + col];
                p[0] = f2tf32(v.x); p[1] = f2tf32(v.y);
                p[2] = f2tf32(v.z); p[3] = f2tf32(v.w);
            }
        }
#pragma unroll
        for (int rr = 0; rr < 2; rr++) {
            int gr = lr + rr * 64;
#pragma unroll
            for (int cc = 0; cc < 2; cc++) {
                int col = lc4 + cc * 16;
                float4 v = *(const float4*)&B[(size_t)gr * KF + kt + col];
                unsigned* p = &Bs[gr * SMSTRIDE + col];
                p[0] = f2tf32(v.x); p[1] = f2tf32(v.y);
                p[2] = f2tf32(v.z); p[3] = f2tf32(v.w);
            }
        }
        __syncthreads();

#pragma unroll
        for (int k8 = 0; k8 < 32; k8 += 8) {
            unsigned a[4][4], b[4][2];
#pragma unroll
            for (int mt = 0; mt < 4; mt++) {
                int mb = warp_m * 64 + mt * 16;
                a[mt][0] = As[(mb + g)     * SMSTRIDE + k8 + tg];
                a[mt][1] = As[(mb + g + 8) * SMSTRIDE + k8 + tg];
                a[mt][2] = As[(mb + g)     * SMSTRIDE + k8 + tg + 4];
                a[mt][3] = As[(mb + g + 8) * SMSTRIDE + k8 + tg + 4];
            }
#pragma unroll
            for (int nt = 0; nt < 4; nt++) {
                int nb = warp_n * 32 + nt * 8;
                b[nt][0] = Bs[(nb + g) * SMSTRIDE + k8 + tg];
                b[nt][1] = Bs[(nb + g) * SMSTRIDE + k8 + tg + 4];
            }
#pragma unroll
            for (int mt = 0; mt < 4; mt++)
#pragma unroll
                for (int nt = 0; nt < 4; nt++) {
                    asm volatile(
                        "mma.sync.aligned.m16n8k8.row.col.f32.tf32.tf32.f32 "
                        "{%0,%1,%2,%3}, {%4,%5,%6,%7}, {%8,%9}, {%0,%1,%2,%3};\n"
                        : "+f"(c[mt][nt][0]), "+f"(c[mt][nt][1]),
                          "+f"(c[mt][nt][2]), "+f"(c[mt][nt][3])
                        : "r"(a[mt][0]), "r"(a[mt][1]), "r"(a[mt][2]), "r"(a[mt][3]),
                          "r"(b[nt][0]), "r"(b[nt][1]));
                }
        }
        __syncthreads();
    }

    // ---- attn weights for this thread's 8 columns (within head warp_n) ----
    float wl[4][2], wr[4][2];
#pragma unroll
    for (int nt = 0; nt < 4; nt++) {
        int col = warp_n * 32 + nt * 8 + 2 * tg;
        wl[nt][0] = attn_l[col];     wl[nt][1] = attn_l[col + 1];
        wr[nt][0] = attn_r[col];     wr[nt][1] = attn_r[col + 1];
    }

    // ---- epilogue: fp16 ft stores + fused el/er (two rows per mt) ----
#pragma unroll
    for (int mt = 0; mt < 4; mt++) {
        int r0 = row0 + warp_m * 64 + mt * 16 + g;

        float el0 = 0.f, er0 = 0.f, el1 = 0.f, er1 = 0.f;
#pragma unroll
        for (int nt = 0; nt < 4; nt++) {
            el0 = fmaf(c[mt][nt][0], wl[nt][0], el0); el0 = fmaf(c[mt][nt][1], wl[nt][1], el0);
            er0 = fmaf(c[mt][nt][0], wr[nt][0], er0); er0 = fmaf(c[mt][nt][1], wr[nt][1], er0);
            el1 = fmaf(c[mt][nt][2], wl[nt][0], el1); el1 = fmaf(c[mt][nt][3], wl[nt][1], el1);
            er1 = fmaf(c[mt][nt][2], wr[nt][0], er1); er1 = fmaf(c[mt][nt][3], wr[nt][1], er1);
        }
        el0 += __shfl_xor_sync(0xffffffffu, el0, 1); el0 += __shfl_xor_sync(0xffffffffu, el0, 2);
        er0 += __shfl_xor_sync(0xffffffffu, er0, 1); er0 += __shfl_xor_sync(0xffffffffu, er0, 2);
        el1 += __shfl_xor_sync(0xffffffffu, el1, 1); el1 += __shfl_xor_sync(0xffffffffu, el1, 2);
        er1 += __shfl_xor_sync(0xffffffffu, er1, 1); er1 += __shfl_xor_sync(0xffffffffu, er1, 2);

#pragma unroll
        for (int nt = 0; nt < 4; nt++) {
            int col = warp_n * 32 + nt * 8 + 2 * tg;
            if (r0 < M)
                *(__half2*)&g_fth[(size_t)r0 * HD + col] =
                    __floats2half2_rn(c[mt][nt][0], c[mt][nt][1]);
            if (r0 + 8 < M)
                *(__half2*)&g_fth[(size_t)(r0 + 8) * HD + col] =
                    __floats2half2_rn(c[mt][nt][2], c[mt][nt][3]);
        }
        if (tg == 0) {
            if (r0 < M)     { g_el[r0 * 4 + warp_n] = el0;       g_er[r0 * 4 + warp_n] = er0; }
            if (r0 + 8 < M) { g_el[(r0 + 8) * 4 + warp_n] = el1; g_er[(r0 + 8) * 4 + warp_n] = er1; }
        }
    }
}

// ================= CSR build: histogram -> scan -> scatter ===================
__global__ void hist_kernel(const int* __restrict__ dst, int E) {
    int e = blockIdx.x * blockDim.x + threadIdx.x;
    if (e < E) atomicAdd(&g_cnt[dst[e]], 1);
}

__global__ void scan1_kernel(int n) {
    __shared__ int sh[256];
    int i = blockIdx.x * 256 + threadIdx.x;
    int v = (i < n) ? g_cnt[i] : 0;
    sh[threadIdx.x] = v;
    __syncthreads();
#pragma unroll
    for (int ofs = 1; ofs < 256; ofs <<= 1) {
        int t = (threadIdx.x >= ofs) ? sh[threadIdx.x - ofs] : 0;
        __syncthreads();
        sh[threadIdx.x] += t;
        __syncthreads();
    }
    if (i < n) g_off[i + 1] = sh[threadIdx.x];
    if (threadIdx.x == 255) g_bsum[blockIdx.x] = sh[255];
}

__global__ void scan2_kernel(int nb) {
    __shared__ int sh[512];
    int t = threadIdx.x;
    int v = (t < nb) ? g_bsum[t] : 0;
    sh[t] = v;
    __syncthreads();
#pragma unroll
    for (int ofs = 1; ofs < 512; ofs <<= 1) {
        int u = (t >= ofs) ? sh[t - ofs] : 0;
        __syncthreads();
        sh[t] += u;
        __syncthreads();
    }
    if (t < nb) g_bsum[t] = sh[t] - v;   // exclusive
}

__global__ void scan3_kernel(int n) {
    int i = blockIdx.x * 256 + threadIdx.x;
    if (i < n) g_off[i + 1] += g_bsum[blockIdx.x];
    if (i == 0) g_off[0] = 0;
}

__global__ void scatter_kernel(const int* __restrict__ src,
                               const int* __restrict__ dst, int E) {
    int e = blockIdx.x * blockDim.x + threadIdx.x;
    if (e >= E) return;
    int d   = dst[e];
    int pos = g_off[d] + atomicAdd(&g_cnt[d], 1);
    g_esrc[pos] = src[e];
}

// ================= fused softmax + aggregate (warp per dst node) =============
__global__ __launch_bounds__(256) void aggregate_kernel(float* __restrict__ out, int N) {
    int d    = (blockIdx.x * blockDim.x + threadIdx.x) >> 5;
    int lane = threadIdx.x & 31;
    if (d >= N) return;

    int beg = g_off[d], end = g_off[d + 1];
    const int h     = lane >> 3;
    const float erd = g_er[d * 4 + h];

    float4 acc = make_float4(0.f, 0.f, 0.f, 0.f);
    float  asum = 0.f;

    for (int p = beg; p < end; ++p) {
        int   s = g_esrc[p];
        float v = g_el[s * 4 + h] + erd;
        v = v > 0.f ? v : 0.2f * v;
        float a = __expf(v);
        asum += a;
        uint2 raw = *(const uint2*)&g_fth[(size_t)s * HD + lane * 4];
        float2 f0 = __half22float2(*(__half2*)&raw.x);
        float2 f1 = __half22float2(*(__half2*)&raw.y);
        acc.x = fmaf(a, f0.x, acc.x);
        acc.y = fmaf(a, f0.y, acc.y);
        acc.z = fmaf(a, f1.x, acc.z);
        acc.w = fmaf(a, f1.y, acc.w);
    }

    float inv = (asum > 0.f) ? (1.f / asum) : 0.f;
    acc.x *= inv; acc.y *= inv; acc.z *= inv; acc.w *= inv;
    *(float4*)&out[(size_t)d * HD + lane * 4] = acc;
}

// ================= launch ====================================================
extern "C" void kernel_launch(void* const* d_in, const int* in_sizes, int n_in,
                              void* d_out, int out_size) {
    const float* feat   = (const float*)d_in[0];
    const float* fc_w   = (const float*)d_in[1];
    const float* attn_l = (const float*)d_in[2];
    const float* attn_r = (const float*)d_in[3];
    const int*   src    = (const int*)d_in[4];
    const int*   dst    = (const int*)d_in[5];
    float*       out    = (float*)d_out;

    int M = in_sizes[0] / KF;   // nodes
    int E = in_sizes[4];        // edges
    int nblk = (M + 255) / 256;

    void* cnt_ptr = nullptr;
    cudaGetSymbolAddress(&cnt_ptr, g_cnt);

    // CSR build by dst
    cudaMemsetAsync(cnt_ptr, 0, (size_t)M * sizeof(int), 0);
    hist_kernel<<<(E + 255) / 256, 256>>>(dst, E);
    scan1_kernel<<<nblk, 256>>>(M);
    scan2_kernel<<<1, 512>>>(nblk);
    scan3_kernel<<<nblk, 256>>>(M);
    cudaMemsetAsync(cnt_ptr, 0, (size_t)M * sizeof(int), 0);
    scatter_kernel<<<(E + 255) / 256, 256>>>(src, dst, E);

    // projection (tf32 tensor cores) + fused logits + fp16 ft
    mma_gemm_kernel<<<(M + 127) / 128, 256>>>(feat, fc_w, attn_l, attn_r, M);

    // fused softmax + aggregation, one warp per dst node
    aggregate_kernel<<<(M * 32 + 255) / 256, 256>>>(out, M);
}

// round 6
// speedup vs baseline: 3.3113x; 1.0937x over previous
#include <cuda_runtime.h>
#include <cuda_fp16.h>
#include <cstdint>

#define NMAX 100000
#define EMAXN 1600000
#define KF 256
#define HD 128

// ---------------- scratch (device globals; no allocs allowed) ----------------
__device__ __half g_fth[(size_t)NMAX * HD]; // projected features fp16 [N,128]
__device__ float g_el[NMAX * 4];            // left logits  [N,4]
__device__ float g_er[NMAX * 4];            // right logits [N,4]
__device__ int   g_cnt[NMAX];               // histogram
__device__ int   g_off[NMAX + 1];           // CSR offsets by dst (destructively shifted by scatter)
__device__ int   g_bsum[512];               // block partial sums
__device__ int   g_boff[512];               // block exclusive prefixes
__device__ int   g_esrc[EMAXN];             // src ids bucketed by dst
__device__ int            g_arrive1, g_arrive2;
__device__ volatile int   g_flag1, g_flag2;

// ================= tf32 tensor-core GEMM (cp.async double-buffered) ==========
// ft = feat[M,256] @ fc_w[128,256]^T ; fused el/er ; fp16 ft output.
// Block tile 128x128, BK=16, 2-stage pipeline, 8 warps (2m x 4n), warp 64x32.
#define BK   16
#define SMS  20   // 16 + 4 pad floats per row

__device__ __forceinline__ unsigned f2tf32(float f) {
    unsigned r;
    asm("cvt.rna.tf32.f32 %0, %1;" : "=r"(r) : "f"(f));
    return r;
}

__device__ __forceinline__ void cp16(unsigned int s, const float* g, bool pred) {
    int sz = pred ? 16 : 0;
    asm volatile("cp.async.ca.shared.global [%0], [%1], 16, %2;\n"
                 :: "r"(s), "l"(g), "r"(sz));
}

__global__ __launch_bounds__(256) void mma_gemm_kernel(const float* __restrict__ A,
                                                       const float* __restrict__ B,
                                                       const float* __restrict__ attn_l,
                                                       const float* __restrict__ attn_r,
                                                       int M) {
    __shared__ float As[2][128 * SMS];
    __shared__ float Bs[2][128 * SMS];

    const int tid    = threadIdx.x;
    const int wid    = tid >> 5;
    const int lane   = tid & 31;
    const int warp_m = wid >> 2;      // 0..1
    const int warp_n = wid & 3;       // 0..3 (head)
    const int g      = lane >> 2;     // 0..7
    const int tg     = lane & 3;      // 0..3

    const int row0 = blockIdx.x * 128;
    const int lr   = tid >> 2;        // 0..63
    const int lc   = (tid & 3) * 4;   // 0,4,8,12

    float c[4][4][4];
#pragma unroll
    for (int i = 0; i < 4; i++)
#pragma unroll
        for (int j = 0; j < 4; j++)
#pragma unroll
            for (int k = 0; k < 4; k++) c[i][j][k] = 0.f;

    // staging rows for this thread
    const int  ar0 = row0 + lr, ar1 = row0 + lr + 64;
    const bool ok0 = (ar0 < M), ok1 = (ar1 < M);
    const float* pa0 = A + (size_t)(ok0 ? ar0 : 0) * KF + lc;
    const float* pa1 = A + (size_t)(ok1 ? ar1 : 0) * KF + lc;
    const float* pb0 = B + (size_t)lr * KF + lc;
    const float* pb1 = B + (size_t)(lr + 64) * KF + lc;

    unsigned int sa0 = (unsigned int)__cvta_generic_to_shared(&As[0][lr * SMS + lc]);
    unsigned int sa1 = (unsigned int)__cvta_generic_to_shared(&As[0][(lr + 64) * SMS + lc]);
    unsigned int sb0 = (unsigned int)__cvta_generic_to_shared(&Bs[0][lr * SMS + lc]);
    unsigned int sb1 = (unsigned int)__cvta_generic_to_shared(&Bs[0][(lr + 64) * SMS + lc]);
    const unsigned int bufstride = 128 * SMS * 4;

    // prologue: stage tile 0 into buffer 0
    cp16(sa0, pa0, ok0); cp16(sa1, pa1, ok1);
    cp16(sb0, pb0, true); cp16(sb1, pb1, true);
    asm volatile("cp.async.commit_group;\n");

    int cur = 0;
    const int NT = KF / BK;   // 16
#pragma unroll 1
    for (int t = 0; t < NT; t++) {
        if (t + 1 < NT) {
            int kt = (t + 1) * BK;
            unsigned int o = (cur ^ 1) * bufstride;
            cp16(sa0 + o, pa0 + kt, ok0); cp16(sa1 + o, pa1 + kt, ok1);
            cp16(sb0 + o, pb0 + kt, true); cp16(sb1 + o, pb1 + kt, true);
            asm volatile("cp.async.commit_group;\n");
            asm volatile("cp.async.wait_group 1;\n");
        } else {
            asm volatile("cp.async.wait_group 0;\n");
        }
        __syncthreads();

        const float* Ab = &As[cur][0];
        const float* Bb = &Bs[cur][0];
#pragma unroll
        for (int k8 = 0; k8 < BK; k8 += 8) {
            unsigned a[4][4], b[4][2];
#pragma unroll
            for (int mt = 0; mt < 4; mt++) {
                int mb = warp_m * 64 + mt * 16;
                a[mt][0] = f2tf32(Ab[(mb + g)     * SMS + k8 + tg]);
                a[mt][1] = f2tf32(Ab[(mb + g + 8) * SMS + k8 + tg]);
                a[mt][2] = f2tf32(Ab[(mb + g)     * SMS + k8 + tg + 4]);
                a[mt][3] = f2tf32(Ab[(mb + g + 8) * SMS + k8 + tg + 4]);
            }
#pragma unroll
            for (int nt = 0; nt < 4; nt++) {
                int nb = warp_n * 32 + nt * 8;
                b[nt][0] = f2tf32(Bb[(nb + g) * SMS + k8 + tg]);
                b[nt][1] = f2tf32(Bb[(nb + g) * SMS + k8 + tg + 4]);
            }
#pragma unroll
            for (int mt = 0; mt < 4; mt++)
#pragma unroll
                for (int nt = 0; nt < 4; nt++) {
                    asm volatile(
                        "mma.sync.aligned.m16n8k8.row.col.f32.tf32.tf32.f32 "
                        "{%0,%1,%2,%3}, {%4,%5,%6,%7}, {%8,%9}, {%0,%1,%2,%3};\n"
                        : "+f"(c[mt][nt][0]), "+f"(c[mt][nt][1]),
                          "+f"(c[mt][nt][2]), "+f"(c[mt][nt][3])
                        : "r"(a[mt][0]), "r"(a[mt][1]), "r"(a[mt][2]), "r"(a[mt][3]),
                          "r"(b[nt][0]), "r"(b[nt][1]));
                }
        }
        __syncthreads();
        cur ^= 1;
    }

    // ---- attn weights for this thread's 8 columns (within head warp_n) ----
    float wl[4][2], wr[4][2];
#pragma unroll
    for (int nt = 0; nt < 4; nt++) {
        int col = warp_n * 32 + nt * 8 + 2 * tg;
        wl[nt][0] = attn_l[col]; wl[nt][1] = attn_l[col + 1];
        wr[nt][0] = attn_r[col]; wr[nt][1] = attn_r[col + 1];
    }

    // ---- epilogue: fp16 ft stores + fused el/er ----
#pragma unroll
    for (int mt = 0; mt < 4; mt++) {
        int r0 = row0 + warp_m * 64 + mt * 16 + g;

        float el0 = 0.f, er0 = 0.f, el1 = 0.f, er1 = 0.f;
#pragma unroll
        for (int nt = 0; nt < 4; nt++) {
            el0 = fmaf(c[mt][nt][0], wl[nt][0], el0); el0 = fmaf(c[mt][nt][1], wl[nt][1], el0);
            er0 = fmaf(c[mt][nt][0], wr[nt][0], er0); er0 = fmaf(c[mt][nt][1], wr[nt][1], er0);
            el1 = fmaf(c[mt][nt][2], wl[nt][0], el1); el1 = fmaf(c[mt][nt][3], wl[nt][1], el1);
            er1 = fmaf(c[mt][nt][2], wr[nt][0], er1); er1 = fmaf(c[mt][nt][3], wr[nt][1], er1);
        }
        el0 += __shfl_xor_sync(0xffffffffu, el0, 1); el0 += __shfl_xor_sync(0xffffffffu, el0, 2);
        er0 += __shfl_xor_sync(0xffffffffu, er0, 1); er0 += __shfl_xor_sync(0xffffffffu, er0, 2);
        el1 += __shfl_xor_sync(0xffffffffu, el1, 1); el1 += __shfl_xor_sync(0xffffffffu, el1, 2);
        er1 += __shfl_xor_sync(0xffffffffu, er1, 1); er1 += __shfl_xor_sync(0xffffffffu, er1, 2);

#pragma unroll
        for (int nt = 0; nt < 4; nt++) {
            int col = warp_n * 32 + nt * 8 + 2 * tg;
            if (r0 < M)
                *(__half2*)&g_fth[(size_t)r0 * HD + col] =
                    __floats2half2_rn(c[mt][nt][0], c[mt][nt][1]);
            if (r0 + 8 < M)
                *(__half2*)&g_fth[(size_t)(r0 + 8) * HD + col] =
                    __floats2half2_rn(c[mt][nt][2], c[mt][nt][3]);
        }
        if (tg == 0) {
            if (r0 < M)     { g_el[r0 * 4 + warp_n] = el0;       g_er[r0 * 4 + warp_n] = er0; }
            if (r0 + 8 < M) { g_el[(r0 + 8) * 4 + warp_n] = el1; g_er[(r0 + 8) * 4 + warp_n] = er1; }
        }
    }
}

// ================= histogram (+ reset of sync state) =========================
__global__ void hist_kernel(const int* __restrict__ dst, int E) {
    if (blockIdx.x == 0 && threadIdx.x == 0) {
        g_arrive1 = 0; g_arrive2 = 0; g_flag1 = 0; g_flag2 = 0;
    }
    int e = blockIdx.x * blockDim.x + threadIdx.x;
    if (e < E) atomicAdd(&g_cnt[dst[e]], 1);
}

// ================= fused scan + scatter (single kernel, grid barriers) =======
// All 391 blocks are co-resident (3 blocks/SM needed << limit) -> spinning safe.
__global__ __launch_bounds__(256) void scan_scatter_kernel(const int* __restrict__ src,
                                                           const int* __restrict__ dst,
                                                           int M, int E, int nblk) {
    __shared__ int sh[256];
    __shared__ int sh2[512];
    __shared__ int s_last;

    const int b = blockIdx.x, t = threadIdx.x;
    const int i = b * 256 + t;

    // ---- in-block inclusive scan of counts ----
    int v = (i < M) ? g_cnt[i] : 0;
    sh[t] = v;
    __syncthreads();
#pragma unroll
    for (int ofs = 1; ofs < 256; ofs <<= 1) {
        int u = (t >= ofs) ? sh[t - ofs] : 0;
        __syncthreads();
        sh[t] += u;
        __syncthreads();
    }
    if (t == 255) g_bsum[b] = sh[255];
    __threadfence();
    __syncthreads();

    // ---- grid barrier 1: last-arriving block scans the partials ----
    if (t == 0) {
        int tk = atomicAdd(&g_arrive1, 1);
        s_last = (tk == nblk - 1) ? 1 : 0;
    }
    __syncthreads();
    if (s_last) {
        int e0 = (t < nblk) ? g_bsum[t] : 0;
        int e1 = (t + 256 < nblk) ? g_bsum[t + 256] : 0;
        sh2[t] = e0; sh2[t + 256] = e1;
        __syncthreads();
#pragma unroll
        for (int ofs = 1; ofs < 512; ofs <<= 1) {
            int u0 = (t >= ofs) ? sh2[t - ofs] : 0;
            int u1 = (t + 256 >= ofs) ? sh2[t + 256 - ofs] : 0;
            __syncthreads();
            sh2[t] += u0; sh2[t + 256] += u1;
            __syncthreads();
        }
        g_boff[t] = sh2[t] - e0;               // exclusive
        g_boff[t + 256] = sh2[t + 256] - e1;
        __threadfence();
        __syncthreads();
        if (t == 0) g_flag1 = 1;
    } else {
        if (t == 0) { while (g_flag1 == 0) {} }
        __syncthreads();
    }
    __threadfence();

    // ---- write global offsets ----
    int prefix = g_boff[b];
    if (i < M) g_off[i + 1] = sh[t] + prefix;
    if (i == 0) g_off[0] = 0;
    __threadfence();
    __syncthreads();

    // ---- grid barrier 2: all offsets visible before scatter ----
    if (t == 0) {
        int tk = atomicAdd(&g_arrive2, 1);
        if (tk == nblk - 1) { __threadfence(); g_flag2 = 1; }
        else { while (g_flag2 == 0) {} }
    }
    __syncthreads();
    __threadfence();

    // ---- destructive scatter: pos = g_off[d]++, shifting g_off by one ----
    const int stride = nblk * 256;
    for (int e = i; e < E; e += stride) {
        int d = dst[e];
        int pos = atomicAdd(&g_off[d], 1);
        g_esrc[pos] = src[e];
    }
}

// ================= fused softmax + aggregate (warp per dst node) =============
// After destructive scatter: beg(d) = (d==0 ? 0 : g_off[d-1]), end(d) = g_off[d].
__global__ __launch_bounds__(256) void aggregate_kernel(float* __restrict__ out, int N) {
    int d    = (blockIdx.x * blockDim.x + threadIdx.x) >> 5;
    int lane = threadIdx.x & 31;
    if (d >= N) return;

    int beg = (d == 0) ? 0 : g_off[d - 1];
    int end = g_off[d];
    const int h     = lane >> 3;
    const float erd = g_er[d * 4 + h];

    float4 acc = make_float4(0.f, 0.f, 0.f, 0.f);
    float  asum = 0.f;

    int p = beg;
    for (; p + 4 <= end; p += 4) {
        int s0 = g_esrc[p], s1 = g_esrc[p + 1], s2 = g_esrc[p + 2], s3 = g_esrc[p + 3];
        uint2 r0 = *(const uint2*)&g_fth[(size_t)s0 * HD + lane * 4];
        uint2 r1 = *(const uint2*)&g_fth[(size_t)s1 * HD + lane * 4];
        uint2 r2 = *(const uint2*)&g_fth[(size_t)s2 * HD + lane * 4];
        uint2 r3 = *(const uint2*)&g_fth[(size_t)s3 * HD + lane * 4];
        float v0 = g_el[s0 * 4 + h] + erd;
        float v1 = g_el[s1 * 4 + h] + erd;
        float v2 = g_el[s2 * 4 + h] + erd;
        float v3 = g_el[s3 * 4 + h] + erd;
        v0 = v0 > 0.f ? v0 : 0.2f * v0; float a0 = __expf(v0);
        v1 = v1 > 0.f ? v1 : 0.2f * v1; float a1 = __expf(v1);
        v2 = v2 > 0.f ? v2 : 0.2f * v2; float a2 = __expf(v2);
        v3 = v3 > 0.f ? v3 : 0.2f * v3; float a3 = __expf(v3);
        asum += (a0 + a1) + (a2 + a3);
        float2 f;
        f = __half22float2(*(__half2*)&r0.x); acc.x = fmaf(a0, f.x, acc.x); acc.y = fmaf(a0, f.y, acc.y);
        f = __half22float2(*(__half2*)&r0.y); acc.z = fmaf(a0, f.x, acc.z); acc.w = fmaf(a0, f.y, acc.w);
        f = __half22float2(*(__half2*)&r1.x); acc.x = fmaf(a1, f.x, acc.x); acc.y = fmaf(a1, f.y, acc.y);
        f = __half22float2(*(__half2*)&r1.y); acc.z = fmaf(a1, f.x, acc.z); acc.w = fmaf(a1, f.y, acc.w);
        f = __half22float2(*(__half2*)&r2.x); acc.x = fmaf(a2, f.x, acc.x); acc.y = fmaf(a2, f.y, acc.y);
        f = __half22float2(*(__half2*)&r2.y); acc.z = fmaf(a2, f.x, acc.z); acc.w = fmaf(a2, f.y, acc.w);
        f = __half22float2(*(__half2*)&r3.x); acc.x = fmaf(a3, f.x, acc.x); acc.y = fmaf(a3, f.y, acc.y);
        f = __half22float2(*(__half2*)&r3.y); acc.z = fmaf(a3, f.x, acc.z); acc.w = fmaf(a3, f.y, acc.w);
    }
    for (; p < end; ++p) {
        int   s = g_esrc[p];
        float v = g_el[s * 4 + h] + erd;
        v = v > 0.f ? v : 0.2f * v;
        float a = __expf(v);
        asum += a;
        uint2 raw = *(const uint2*)&g_fth[(size_t)s * HD + lane * 4];
        float2 f0 = __half22float2(*(__half2*)&raw.x);
        float2 f1 = __half22float2(*(__half2*)&raw.y);
        acc.x = fmaf(a, f0.x, acc.x); acc.y = fmaf(a, f0.y, acc.y);
        acc.z = fmaf(a, f1.x, acc.z); acc.w = fmaf(a, f1.y, acc.w);
    }

    float inv = (asum > 0.f) ? (1.f / asum) : 0.f;
    acc.x *= inv; acc.y *= inv; acc.z *= inv; acc.w *= inv;
    *(float4*)&out[(size_t)d * HD + lane * 4] = acc;
}

// ================= launch ====================================================
extern "C" void kernel_launch(void* const* d_in, const int* in_sizes, int n_in,
                              void* d_out, int out_size) {
    const float* feat   = (const float*)d_in[0];
    const float* fc_w   = (const float*)d_in[1];
    const float* attn_l = (const float*)d_in[2];
    const float* attn_r = (const float*)d_in[3];
    const int*   src    = (const int*)d_in[4];
    const int*   dst    = (const int*)d_in[5];
    float*       out    = (float*)d_out;

    int M = in_sizes[0] / KF;   // nodes
    int E = in_sizes[4];        // edges
    int nblk = (M + 255) / 256;

    void* cnt_ptr = nullptr;
    cudaGetSymbolAddress(&cnt_ptr, g_cnt);
    cudaMemsetAsync(cnt_ptr, 0, (size_t)M * sizeof(int), 0);

    // projection (tf32 MMA, cp.async pipelined) + fused logits + fp16 ft
    mma_gemm_kernel<<<(M + 127) / 128, 256>>>(feat, fc_w, attn_l, attn_r, M);

    // CSR build: histogram, then fused scan+scatter (grid-barrier kernel)
    hist_kernel<<<(E + 255) / 256, 256>>>(dst, E);
    scan_scatter_kernel<<<nblk, 256>>>(src, dst, M, E, nblk);

    // fused softmax + aggregation, one warp per dst node
    aggregate_kernel<<<(M * 32 + 255) / 256, 256>>>(out, M);
}